// round 14
// baseline (speedup 1.0000x reference)
#include <cuda_runtime.h>

// Problem constants (fixed by reference setup_inputs)
#define BB 128
#define SS 256
#define HH 768
#define KK 64
#define NROWS (BB * SS)     // 32768
#define V4_PER_ROW (HH / 4) // 192

// R14 A/B: __stwt (write-through) instead of __stcs on the 302 MB of
// write-once output. Write-once data never re-read in-kernel: wt avoids
// leaving dirty L2 lines that must drain later (double-handling), the one
// mechanism left that could raise effective write throughput. Everything
// else identical to the converged R9/R13 kernel.
//
// One block per (b,s) row, 192 threads (6 warps), one float4 per thread.
// Membership by warp 0 only: 3x int2 L2-hit loads, 3 ballots; lane 0 folds
// weights into three multipliers + skip flag in smem; one __syncthreads;
// broadcast LDS. Read-skip: s!=0 && !dep && !dpd rows (~60%) are all-zero
// in all three outputs -> store zeros, skip the 3 KB input read.
//
// Validity: indices lie in [0, S) and target = s-1 <= S-2, so idx == S-1
// never matches -- identical to the reference's (idx + 1 < S) check.
__global__ __launch_bounds__(V4_PER_ROW) void fused_kernel(
    const float4* __restrict__ in,
    const int*    __restrict__ depend,
    const int*    __restrict__ depended,
    const int*    __restrict__ noconn,
    const float*  __restrict__ dep_w,
    const float*  __restrict__ dpd_w,
    float4*       __restrict__ out)
{
    const unsigned row = blockIdx.x;
    const unsigned t   = threadIdx.x;

    __shared__ float sh_m[3];
    __shared__ int   sh_skip;

    // membership: warp 0 only
    if (t < 32) {
        const int b      = row >> 8;        // row / SS
        const int s      = row & (SS - 1);  // row % SS
        const int target = s - 1;           // s=0 -> -1, never matches

        const float w1 = __ldg(&dep_w[b]);
        const float w2 = __ldg(&dpd_w[b]);

        const int2 d2 = __ldg(&((const int2*)(depend   + b * KK))[t]);
        const int2 e2 = __ldg(&((const int2*)(depended + b * KK))[t]);
        const int2 n2 = __ldg(&((const int2*)(noconn   + b * KK))[t]);

        const bool dep = __ballot_sync(0xffffffffu,
                            (d2.x == target) | (d2.y == target)) != 0;
        const bool dpd = __ballot_sync(0xffffffffu,
                            (e2.x == target) | (e2.y == target)) != 0;
        const bool noc = __ballot_sync(0xffffffffu,
                            (n2.x == target) | (n2.y == target)) != 0;

        if (t == 0) {
            const bool p0 = (s == 0);
            sh_m[0] = (p0 || dep) ? 1.0f : 0.0f;
            sh_m[1] = (p0 || dpd) ? 1.0f : 0.0f;
            float m2 = dep ? w1 : 0.0f;
            if (dpd) m2 = w2;
            if (noc) m2 = 0.0f;
            if (p0)  m2 = 1.0f;
            sh_m[2] = m2;
            sh_skip = (!p0 && !dep && !dpd) ? 1 : 0;
        }
    }
    __syncthreads();

    const unsigned idx = row * V4_PER_ROW + t;
    const unsigned N4  = NROWS * V4_PER_ROW;

    if (sh_skip) {
        // all three outputs zero for this row: no input read needed
        const float4 z = make_float4(0.0f, 0.0f, 0.0f, 0.0f);
        __stwt(&out[idx],           z);
        __stwt(&out[N4 + idx],      z);
        __stwt(&out[2u * N4 + idx], z);
        return;
    }

    const float m0 = sh_m[0];
    const float m1 = sh_m[1];
    const float m2 = sh_m[2];

    const float4 v = __ldcs(&in[idx]);   // read-once: evict-first

    float4 a, bb, c;
    a.x  = v.x * m0; a.y  = v.y * m0; a.z  = v.z * m0; a.w  = v.w * m0;
    bb.x = v.x * m1; bb.y = v.y * m1; bb.z = v.z * m1; bb.w = v.w * m1;
    c.x  = v.x * m2; c.y  = v.y * m2; c.z  = v.z * m2; c.w  = v.w * m2;

    __stwt(&out[idx],           a);      // write-through: no dirty L2 line
    __stwt(&out[N4 + idx],      bb);
    __stwt(&out[2u * N4 + idx], c);
}

extern "C" void kernel_launch(void* const* d_in, const int* in_sizes, int n_in,
                              void* d_out, int out_size) {
    const float* bert     = (const float*)d_in[0];
    const int*   depend   = (const int*)d_in[1];
    const int*   depended = (const int*)d_in[2];
    const int*   noconn   = (const int*)d_in[3];
    const float* dep_w    = (const float*)d_in[4];
    const float* dpd_w    = (const float*)d_in[5];
    float*       out      = (float*)d_out;

    fused_kernel<<<NROWS, V4_PER_ROW>>>((const float4*)bert, depend, depended,
                                        noconn, dep_w, dpd_w, (float4*)out);
}

// round 15
// speedup vs baseline: 1.0240x; 1.0240x over previous
#include <cuda_runtime.h>

// Problem constants (fixed by reference setup_inputs)
#define BB 128
#define SS 256
#define HH 768
#define KK 64
#define NROWS (BB * SS)     // 32768
#define V4_PER_ROW (HH / 4) // 192

// FINAL kernel — converged at the HBM write-bandwidth floor.
// ncu 52.6-54.0us across runs vs ~53us modeled floor (345 MB mandatory
// traffic: 302 MB irreducible writes + ~40 MB surviving reads, at the
// measured ~6.5 TB/s effective 88%-write-mix throughput).
//
// Structure (each element A/B-measured across R1-R14):
//  - One block per (b,s) row, 192 threads (6 warps), one float4/thread.
//  - Membership by warp 0 only: 3x int2 L2-hit loads (2 entries/lane/list),
//    3 ballots; lane 0 folds weights into three multipliers + skip flag in
//    smem; one __syncthreads; all threads read broadcast LDS values.
//  - Read-skip: a row is all-zero in ALL THREE outputs iff
//    s != 0 && !dep && !dpd (m2 only nonzero via dep/dpd). ~60% of rows ->
//    store zeros, skip the 3 KB input read. Block-uniform branch.
//  - __ldcs read-once input, __stcs write-once outputs (wt measured neutral).
//
// Validity: indices lie in [0, S) and target = s-1 <= S-2, so idx == S-1
// never matches -- identical to the reference's (idx + 1 < S) check.
__global__ __launch_bounds__(V4_PER_ROW) void fused_kernel(
    const float4* __restrict__ in,
    const int*    __restrict__ depend,
    const int*    __restrict__ depended,
    const int*    __restrict__ noconn,
    const float*  __restrict__ dep_w,
    const float*  __restrict__ dpd_w,
    float4*       __restrict__ out)
{
    const unsigned row = blockIdx.x;
    const unsigned t   = threadIdx.x;

    __shared__ float sh_m[3];
    __shared__ int   sh_skip;

    // membership: warp 0 only
    if (t < 32) {
        const int b      = row >> 8;        // row / SS
        const int s      = row & (SS - 1);  // row % SS
        const int target = s - 1;           // s=0 -> -1, never matches

        const float w1 = __ldg(&dep_w[b]);
        const float w2 = __ldg(&dpd_w[b]);

        const int2 d2 = __ldg(&((const int2*)(depend   + b * KK))[t]);
        const int2 e2 = __ldg(&((const int2*)(depended + b * KK))[t]);
        const int2 n2 = __ldg(&((const int2*)(noconn   + b * KK))[t]);

        const bool dep = __ballot_sync(0xffffffffu,
                            (d2.x == target) | (d2.y == target)) != 0;
        const bool dpd = __ballot_sync(0xffffffffu,
                            (e2.x == target) | (e2.y == target)) != 0;
        const bool noc = __ballot_sync(0xffffffffu,
                            (n2.x == target) | (n2.y == target)) != 0;

        if (t == 0) {
            const bool p0 = (s == 0);
            sh_m[0] = (p0 || dep) ? 1.0f : 0.0f;
            sh_m[1] = (p0 || dpd) ? 1.0f : 0.0f;
            float m2 = dep ? w1 : 0.0f;
            if (dpd) m2 = w2;
            if (noc) m2 = 0.0f;
            if (p0)  m2 = 1.0f;
            sh_m[2] = m2;
            sh_skip = (!p0 && !dep && !dpd) ? 1 : 0;
        }
    }
    __syncthreads();

    const unsigned idx = row * V4_PER_ROW + t;
    const unsigned N4  = NROWS * V4_PER_ROW;

    if (sh_skip) {
        // all three outputs zero for this row: no input read needed
        const float4 z = make_float4(0.0f, 0.0f, 0.0f, 0.0f);
        __stcs(&out[idx],           z);
        __stcs(&out[N4 + idx],      z);
        __stcs(&out[2u * N4 + idx], z);
        return;
    }

    const float m0 = sh_m[0];
    const float m1 = sh_m[1];
    const float m2 = sh_m[2];

    const float4 v = __ldcs(&in[idx]);   // read-once: evict-first

    float4 a, bb, c;
    a.x  = v.x * m0; a.y  = v.y * m0; a.z  = v.z * m0; a.w  = v.w * m0;
    bb.x = v.x * m1; bb.y = v.y * m1; bb.z = v.z * m1; bb.w = v.w * m1;
    c.x  = v.x * m2; c.y  = v.y * m2; c.z  = v.z * m2; c.w  = v.w * m2;

    __stcs(&out[idx],           a);      // write-once: evict-first
    __stcs(&out[N4 + idx],      bb);
    __stcs(&out[2u * N4 + idx], c);
}

extern "C" void kernel_launch(void* const* d_in, const int* in_sizes, int n_in,
                              void* d_out, int out_size) {
    const float* bert     = (const float*)d_in[0];
    const int*   depend   = (const int*)d_in[1];
    const int*   depended = (const int*)d_in[2];
    const int*   noconn   = (const int*)d_in[3];
    const float* dep_w    = (const float*)d_in[4];
    const float* dpd_w    = (const float*)d_in[5];
    float*       out      = (float*)d_out;

    fused_kernel<<<NROWS, V4_PER_ROW>>>((const float4*)bert, depend, depended,
                                        noconn, dep_w, dpd_w, (float4*)out);
}

// round 16
// speedup vs baseline: 1.0287x; 1.0046x over previous
#include <cuda_runtime.h>

// Problem constants (fixed by reference setup_inputs)
#define BB 128
#define SS 256
#define HH 768
#define KK 64
#define NROWS (BB * SS)     // 32768
#define V4_PER_ROW (HH / 4) // 192

// FINAL kernel — converged at the HBM write-bandwidth floor.
// ncu 52.6-54.0us over 6 runs vs ~53us analytic floor (345 MB mandatory
// traffic: 302 MB irreducible writes + ~40 MB surviving reads, at the
// measured ~6.5 TB/s effective 88%-write-mix throughput). Issue/ALU/FMA
// all <14% -- byte-limited, no pipe with headroom to convert.
//
// Structure (each element A/B-measured across R1-R14):
//  - One block per (b,s) row, 192 threads (6 warps), one float4/thread.
//  - Membership by warp 0 only: 3x int2 L2-hit loads (2 entries/lane/list),
//    3 ballots; lane 0 folds weights into three multipliers + skip flag in
//    smem; one __syncthreads; all threads read broadcast LDS values.
//  - Read-skip: a row is all-zero in ALL THREE outputs iff
//    s != 0 && !dep && !dpd (m2 only nonzero via dep/dpd). ~60% of rows ->
//    store zeros, skip the 3 KB input read. Block-uniform branch.
//  - __ldcs read-once input, __stcs write-once outputs (wt measured neutral).
//
// Validity: indices lie in [0, S) and target = s-1 <= S-2, so idx == S-1
// never matches -- identical to the reference's (idx + 1 < S) check.
__global__ __launch_bounds__(V4_PER_ROW) void fused_kernel(
    const float4* __restrict__ in,
    const int*    __restrict__ depend,
    const int*    __restrict__ depended,
    const int*    __restrict__ noconn,
    const float*  __restrict__ dep_w,
    const float*  __restrict__ dpd_w,
    float4*       __restrict__ out)
{
    const unsigned row = blockIdx.x;
    const unsigned t   = threadIdx.x;

    __shared__ float sh_m[3];
    __shared__ int   sh_skip;

    // membership: warp 0 only
    if (t < 32) {
        const int b      = row >> 8;        // row / SS
        const int s      = row & (SS - 1);  // row % SS
        const int target = s - 1;           // s=0 -> -1, never matches

        const float w1 = __ldg(&dep_w[b]);
        const float w2 = __ldg(&dpd_w[b]);

        const int2 d2 = __ldg(&((const int2*)(depend   + b * KK))[t]);
        const int2 e2 = __ldg(&((const int2*)(depended + b * KK))[t]);
        const int2 n2 = __ldg(&((const int2*)(noconn   + b * KK))[t]);

        const bool dep = __ballot_sync(0xffffffffu,
                            (d2.x == target) | (d2.y == target)) != 0;
        const bool dpd = __ballot_sync(0xffffffffu,
                            (e2.x == target) | (e2.y == target)) != 0;
        const bool noc = __ballot_sync(0xffffffffu,
                            (n2.x == target) | (n2.y == target)) != 0;

        if (t == 0) {
            const bool p0 = (s == 0);
            sh_m[0] = (p0 || dep) ? 1.0f : 0.0f;
            sh_m[1] = (p0 || dpd) ? 1.0f : 0.0f;
            float m2 = dep ? w1 : 0.0f;
            if (dpd) m2 = w2;
            if (noc) m2 = 0.0f;
            if (p0)  m2 = 1.0f;
            sh_m[2] = m2;
            sh_skip = (!p0 && !dep && !dpd) ? 1 : 0;
        }
    }
    __syncthreads();

    const unsigned idx = row * V4_PER_ROW + t;
    const unsigned N4  = NROWS * V4_PER_ROW;

    if (sh_skip) {
        // all three outputs zero for this row: no input read needed
        const float4 z = make_float4(0.0f, 0.0f, 0.0f, 0.0f);
        __stcs(&out[idx],           z);
        __stcs(&out[N4 + idx],      z);
        __stcs(&out[2u * N4 + idx], z);
        return;
    }

    const float m0 = sh_m[0];
    const float m1 = sh_m[1];
    const float m2 = sh_m[2];

    const float4 v = __ldcs(&in[idx]);   // read-once: evict-first

    float4 a, bb, c;
    a.x  = v.x * m0; a.y  = v.y * m0; a.z  = v.z * m0; a.w  = v.w * m0;
    bb.x = v.x * m1; bb.y = v.y * m1; bb.z = v.z * m1; bb.w = v.w * m1;
    c.x  = v.x * m2; c.y  = v.y * m2; c.z  = v.z * m2; c.w  = v.w * m2;

    __stcs(&out[idx],           a);      // write-once: evict-first
    __stcs(&out[N4 + idx],      bb);
    __stcs(&out[2u * N4 + idx], c);
}

extern "C" void kernel_launch(void* const* d_in, const int* in_sizes, int n_in,
                              void* d_out, int out_size) {
    const float* bert     = (const float*)d_in[0];
    const int*   depend   = (const int*)d_in[1];
    const int*   depended = (const int*)d_in[2];
    const int*   noconn   = (const int*)d_in[3];
    const float* dep_w    = (const float*)d_in[4];
    const float* dpd_w    = (const float*)d_in[5];
    float*       out      = (float*)d_out;

    fused_kernel<<<NROWS, V4_PER_ROW>>>((const float4*)bert, depend, depended,
                                        noconn, dep_w, dpd_w, (float4*)out);
}